// round 16
// baseline (speedup 1.0000x reference)
#include <cuda_runtime.h>
#include <cuda_fp16.h>
#include <math.h>

#define T_ 256
#define B_ 128
#define I_ 1024
#define H_ 1024
#define P_ 512
#define G_ 4096  /* 4*H */

#define NBLK 128
#define STHR 128   /* recurrence kernel threads: 4 independent mma warps */
#define XPAD 8
#define HFT 16384  /* uint4 per timestep in g_hf: B*H fp16 /8 */

// ---------------- globals (no allocation) ----------------
__device__ float g_xg[(size_t)T_ * B_ * G_];     // [T*B, 4H] input gate contributions
__device__ float g_wc[(size_t)G_ * H_];          // W_comb = Whh @ Whr  [4096,1024] fp32
__device__ uint4 g_hf[(size_t)T_ * HFT];         // hfull, fp16 bits, k16 mma-fragment layout
__device__ uint2 g_wf[4 * 64 * 16 * 32];         // Whr fp16 B-fragments (1 MB)
__device__ int g_flags[NBLK * 8];                // per-CTA warp-arrival counters (32B stride)

// ---------------- helpers ----------------
__device__ __forceinline__ unsigned f2tf(float x) {
    unsigned r;
    asm("cvt.rna.tf32.f32 %0, %1;" : "=r"(r) : "f"(x));
    return r;
}

__device__ __forceinline__ unsigned f2h2(float lo, float hi) {
    __half2 h = __floats2half2_rn(lo, hi);
    return *(unsigned*)&h;
}

__device__ __forceinline__ void mma_tf32(float* c, const unsigned* a, const unsigned* b) {
    asm volatile(
        "mma.sync.aligned.m16n8k8.row.col.f32.tf32.tf32.f32 "
        "{%0,%1,%2,%3},{%4,%5,%6,%7},{%8,%9},{%0,%1,%2,%3};"
        : "+f"(c[0]), "+f"(c[1]), "+f"(c[2]), "+f"(c[3])
        : "r"(a[0]), "r"(a[1]), "r"(a[2]), "r"(a[3]), "r"(b[0]), "r"(b[1]));
}

__device__ __forceinline__ void mma_f16(float* c, const unsigned* a, const unsigned* b) {
    asm volatile(
        "mma.sync.aligned.m16n8k16.row.col.f32.f16.f16.f32 "
        "{%0,%1,%2,%3},{%4,%5,%6,%7},{%8,%9},{%0,%1,%2,%3};"
        : "+f"(c[0]), "+f"(c[1]), "+f"(c[2]), "+f"(c[3])
        : "r"(a[0]), "r"(a[1]), "r"(a[2]), "r"(a[3]), "r"(b[0]), "r"(b[1]));
}

// fast-math epilogue transcendentals (err ~1e-5 << fp16 noise 4.2e-4)
__device__ __forceinline__ float fsig(float x) {
    float e = __expf(-x);
    return __fdividef(1.0f, 1.0f + e);
}
__device__ __forceinline__ float ftanh(float x) {
    x = fminf(fmaxf(x, -15.0f), 15.0f);
    float e = __expf(2.0f * x);
    return __fdividef(e - 1.0f, e + 1.0f);
}

__device__ __forceinline__ unsigned smem_u32(const void* p) {
    return (unsigned)__cvta_generic_to_shared(p);
}

__device__ __forceinline__ void cp_async16(unsigned dst, const void* src) {
    asm volatile("cp.async.cg.shared.global [%0], [%1], 16;" :: "r"(dst), "l"(src));
}
__device__ __forceinline__ void cp_commit() { asm volatile("cp.async.commit_group;"); }
template<int N> __device__ __forceinline__ void cp_wait() {
    asm volatile("cp.async.wait_group %0;" :: "n"(N));
}

__device__ __forceinline__ int ld_acq(const int* p) {
    int v;
    asm volatile("ld.global.acquire.gpu.b32 %0, [%1];" : "=r"(v) : "l"(p) : "memory");
    return v;
}
__device__ __forceinline__ void red_add_rel(int* p, int v) {
    asm volatile("red.add.release.gpu.global.s32 [%0], %1;" :: "l"(p), "r"(v) : "memory");
}

// ---------------- init: flag reset ----------------
__global__ void init_kernel() {
    int i = blockIdx.x * blockDim.x + threadIdx.x;
    if (i < NBLK * 8) g_flags[i] = 0;
}

// ---------------- Whr -> fp16 B-fragment pack (one-time, 1 MB) ----------------
__global__ __launch_bounds__(256) void whr_pack_kernel(const float* __restrict__ Whr) {
    int idx = blockIdx.x * 256 + threadIdx.x;
    int bn4 = idx >> 15;
    int kt  = (idx >> 9) & 63;
    int j   = (idx >> 5) & 15;
    int l   = idx & 31;
    int gg = l >> 2, cc = l & 3;
    const float* wr = Whr + (size_t)(bn4 * 128 + 8 * j + gg) * H_ + kt * 16;
    g_wf[idx] = make_uint2(f2h2(wr[2 * cc], wr[2 * cc + 1]),
                           f2h2(wr[2 * cc + 8], wr[2 * cc + 9]));
}

// ---------------- xg = x @ W_ih^T (+ h0 @ Whh^T fold for t=0) via FP16 mma ----------------
#define XAS 24
__global__ __launch_bounds__(256) void xg_mma_kernel(const float* __restrict__ X,
                                                     const float* __restrict__ Wih,
                                                     const float* __restrict__ h0,
                                                     const float* __restrict__ Whh) {
    const int K = I_, N = G_;
    __shared__ __half As[2][128][XAS];
    __shared__ __half Bs[2][128][XAS];

    const int bm = blockIdx.y * 128;
    const int bn = blockIdx.x * 128;
    const int tid = threadIdx.x;
    const int lane = tid & 31, wid = tid >> 5;
    const int wm = (wid >> 2) * 64, wn = (wid & 3) * 32;
    const int g = lane >> 2, c = lane & 3;
    const int srow = tid >> 2;
    const int skq = (tid & 3) * 4;

    float acc[4][4][4];
#pragma unroll
    for (int i = 0; i < 4; i++)
#pragma unroll
        for (int j = 0; j < 4; j++)
#pragma unroll
            for (int r = 0; r < 4; r++) acc[i][j][r] = 0.0f;

    float4 pa[2], pb[2];
#pragma unroll
    for (int it = 0; it < 2; it++) {
        int row = it * 64 + srow;
        pa[it] = *(const float4*)(X + (size_t)(bm + row) * K + skq);
        pb[it] = *(const float4*)(Wih + (size_t)(bn + row) * K + skq);
    }

    for (int kt = 0; kt < K / 16; kt++) {
        int buf = kt & 1;
#pragma unroll
        for (int it = 0; it < 2; it++) {
            int row = it * 64 + srow;
            uint2 ua, ub;
            ua.x = f2h2(pa[it].x, pa[it].y); ua.y = f2h2(pa[it].z, pa[it].w);
            ub.x = f2h2(pb[it].x, pb[it].y); ub.y = f2h2(pb[it].z, pb[it].w);
            *(uint2*)&As[buf][row][skq] = ua;
            *(uint2*)&Bs[buf][row][skq] = ub;
        }
        __syncthreads();
        if (kt < K / 16 - 1) {
            int k0 = (kt + 1) * 16;
#pragma unroll
            for (int it = 0; it < 2; it++) {
                int row = it * 64 + srow;
                pa[it] = *(const float4*)(X + (size_t)(bm + row) * K + k0 + skq);
                pb[it] = *(const float4*)(Wih + (size_t)(bn + row) * K + k0 + skq);
            }
        }
        unsigned a[4][4], b[4][2];
#pragma unroll
        for (int i = 0; i < 4; i++) {
            int m = wm + i * 16;
            a[i][0] = *(const unsigned*)&As[buf][m + g][2 * c];
            a[i][1] = *(const unsigned*)&As[buf][m + g + 8][2 * c];
            a[i][2] = *(const unsigned*)&As[buf][m + g][2 * c + 8];
            a[i][3] = *(const unsigned*)&As[buf][m + g + 8][2 * c + 8];
        }
#pragma unroll
        for (int j = 0; j < 4; j++) {
            int n = wn + j * 8;
            b[j][0] = *(const unsigned*)&Bs[buf][n + g][2 * c];
            b[j][1] = *(const unsigned*)&Bs[buf][n + g][2 * c + 8];
        }
#pragma unroll
        for (int i = 0; i < 4; i++)
#pragma unroll
            for (int j = 0; j < 4; j++) mma_f16(acc[i][j], a[i], b[j]);
    }

    // ---- t=0 fold: += h0 @ Whh^T (K=512), same staging ----
    if (bm == 0) {
        __syncthreads();
#pragma unroll
        for (int it = 0; it < 2; it++) {
            int row = it * 64 + srow;
            pa[it] = *(const float4*)(h0 + (size_t)row * P_ + skq);
            pb[it] = *(const float4*)(Whh + (size_t)(bn + row) * P_ + skq);
        }
        for (int kt = 0; kt < P_ / 16; kt++) {
            int buf = kt & 1;
#pragma unroll
            for (int it = 0; it < 2; it++) {
                int row = it * 64 + srow;
                uint2 ua, ub;
                ua.x = f2h2(pa[it].x, pa[it].y); ua.y = f2h2(pa[it].z, pa[it].w);
                ub.x = f2h2(pb[it].x, pb[it].y); ub.y = f2h2(pb[it].z, pb[it].w);
                *(uint2*)&As[buf][row][skq] = ua;
                *(uint2*)&Bs[buf][row][skq] = ub;
            }
            __syncthreads();
            if (kt < P_ / 16 - 1) {
                int k0 = (kt + 1) * 16;
#pragma unroll
                for (int it = 0; it < 2; it++) {
                    int row = it * 64 + srow;
                    pa[it] = *(const float4*)(h0 + (size_t)row * P_ + k0 + skq);
                    pb[it] = *(const float4*)(Whh + (size_t)(bn + row) * P_ + k0 + skq);
                }
            }
            unsigned a[4][4], b[4][2];
#pragma unroll
            for (int i = 0; i < 4; i++) {
                int m = wm + i * 16;
                a[i][0] = *(const unsigned*)&As[buf][m + g][2 * c];
                a[i][1] = *(const unsigned*)&As[buf][m + g + 8][2 * c];
                a[i][2] = *(const unsigned*)&As[buf][m + g][2 * c + 8];
                a[i][3] = *(const unsigned*)&As[buf][m + g + 8][2 * c + 8];
            }
#pragma unroll
            for (int j = 0; j < 4; j++) {
                int n = wn + j * 8;
                b[j][0] = *(const unsigned*)&Bs[buf][n + g][2 * c];
                b[j][1] = *(const unsigned*)&Bs[buf][n + g][2 * c + 8];
            }
#pragma unroll
            for (int i = 0; i < 4; i++)
#pragma unroll
                for (int j = 0; j < 4; j++) mma_f16(acc[i][j], a[i], b[j]);
        }
    }

#pragma unroll
    for (int i = 0; i < 4; i++) {
        int r0 = bm + wm + i * 16 + g;
#pragma unroll
        for (int j = 0; j < 4; j++) {
            int cc = bn + wn + j * 8 + c * 2;
            *(float2*)(g_xg + (size_t)r0 * N + cc)       = make_float2(acc[i][j][0], acc[i][j][1]);
            *(float2*)(g_xg + (size_t)(r0 + 8) * N + cc) = make_float2(acc[i][j][2], acc[i][j][3]);
        }
    }
}

// ---------------- W_comb = Whh @ Whr  (3xTF32, proven) ----------------
__global__ __launch_bounds__(256) void wcomb_mma_kernel(const float* __restrict__ Whh,
                                                        const float* __restrict__ Whr) {
    __shared__ unsigned Ah[16][128 + XPAD], Al[16][128 + XPAD];
    __shared__ unsigned Bh[16][128 + XPAD], Bl[16][128 + XPAD];

    const int bm = blockIdx.y * 128;
    const int bn = blockIdx.x * 128;
    const int tid = threadIdx.x;
    const int lane = tid & 31, wid = tid >> 5;
    const int wm = (wid >> 2) * 64, wn = (wid & 3) * 32;
    const int g = lane >> 2, c = lane & 3;

    float acc[4][4][4];
#pragma unroll
    for (int i = 0; i < 4; i++)
#pragma unroll
        for (int j = 0; j < 4; j++)
#pragma unroll
            for (int r = 0; r < 4; r++) acc[i][j][r] = 0.0f;

    for (int k0 = 0; k0 < P_; k0 += 16) {
#pragma unroll
        for (int it = 0; it < 2; it++) {
            int idx = it * 256 + tid;
            {
                int row = idx >> 2;
                int kq = (idx & 3) * 4;
                float4 v = *(const float4*)(Whh + (size_t)(bm + row) * P_ + k0 + kq);
                float h0 = __uint_as_float(f2tf(v.x)), h1 = __uint_as_float(f2tf(v.y));
                float h2 = __uint_as_float(f2tf(v.z)), h3 = __uint_as_float(f2tf(v.w));
                Ah[kq + 0][row] = __float_as_uint(h0); Al[kq + 0][row] = f2tf(v.x - h0);
                Ah[kq + 1][row] = __float_as_uint(h1); Al[kq + 1][row] = f2tf(v.y - h1);
                Ah[kq + 2][row] = __float_as_uint(h2); Al[kq + 2][row] = f2tf(v.z - h2);
                Ah[kq + 3][row] = __float_as_uint(h3); Al[kq + 3][row] = f2tf(v.w - h3);
            }
            {
                int k = idx >> 5;
                int n4 = (idx & 31) * 4;
                float4 v = *(const float4*)(Whr + (size_t)(k0 + k) * H_ + bn + n4);
                float h0 = __uint_as_float(f2tf(v.x)), h1 = __uint_as_float(f2tf(v.y));
                float h2 = __uint_as_float(f2tf(v.z)), h3 = __uint_as_float(f2tf(v.w));
                Bh[k][n4 + 0] = __float_as_uint(h0); Bl[k][n4 + 0] = f2tf(v.x - h0);
                Bh[k][n4 + 1] = __float_as_uint(h1); Bl[k][n4 + 1] = f2tf(v.y - h1);
                Bh[k][n4 + 2] = __float_as_uint(h2); Bl[k][n4 + 2] = f2tf(v.z - h2);
                Bh[k][n4 + 3] = __float_as_uint(h3); Bl[k][n4 + 3] = f2tf(v.w - h3);
            }
        }
        __syncthreads();
#pragma unroll
        for (int kk = 0; kk < 16; kk += 8) {
            unsigned ah[4][4], al[4][4], bh[4][2], bl[4][2];
#pragma unroll
            for (int i = 0; i < 4; i++) {
                int m = wm + i * 16;
                ah[i][0] = Ah[kk + c][m + g];     al[i][0] = Al[kk + c][m + g];
                ah[i][1] = Ah[kk + c][m + g + 8]; al[i][1] = Al[kk + c][m + g + 8];
                ah[i][2] = Ah[kk + c + 4][m + g]; al[i][2] = Al[kk + c + 4][m + g];
                ah[i][3] = Ah[kk + c + 4][m + g + 8]; al[i][3] = Al[kk + c + 4][m + g + 8];
            }
#pragma unroll
            for (int j = 0; j < 4; j++) {
                int n = wn + j * 8;
                bh[j][0] = Bh[kk + c][n + g];     bl[j][0] = Bl[kk + c][n + g];
                bh[j][1] = Bh[kk + 4 + c][n + g]; bl[j][1] = Bl[kk + 4 + c][n + g];
            }
#pragma unroll
            for (int i = 0; i < 4; i++)
#pragma unroll
                for (int j = 0; j < 4; j++) {
                    mma_tf32(acc[i][j], al[i], bh[j]);
                    mma_tf32(acc[i][j], ah[i], bl[j]);
                    mma_tf32(acc[i][j], ah[i], bh[j]);
                }
        }
        __syncthreads();
    }

#pragma unroll
    for (int i = 0; i < 4; i++) {
        int r0 = bm + wm + i * 16 + g;
#pragma unroll
        for (int j = 0; j < 4; j++) {
            int cc = bn + wn + j * 8 + c * 2;
            *(float2*)(g_wc + (size_t)r0 * H_ + cc)       = make_float2(acc[i][j][0], acc[i][j][1]);
            *(float2*)(g_wc + (size_t)(r0 + 8) * H_ + cc) = make_float2(acc[i][j][2], acc[i][j][3]);
        }
    }
}

// ---------------- persistent recurrence: fully warp-independent steps ----------------
// 4 warps per CTA, each owning 16 batch rows; NO syncthreads in the step loop.
// Publish: lane0 of each warp red.add.release(+1) on flags[bid] after its hfull stores.
// Consume: every warp independently acquire-polls all 128 counters for >= 4t.
__global__ __launch_bounds__(STHR, 1) void lstm_seq_kernel(const float* __restrict__ c0,
                                                           float* __restrict__ out) {
    extern __shared__ __align__(16) unsigned smraw[];
    uint4* Wb   = (uint4*)smraw;             // [8192] W frags (128 KB)
    uint4* Abuf = Wb + 8192;                 // [4 warps][4 slots][8 kt][32 lanes] (64 KB)
    float* c_s  = (float*)(Abuf + 4096);     // [64][16] stride 17 cell state (warp-exclusive rows)

    const int bid = blockIdx.x;
    const int tid = threadIdx.x;
    const int lane = tid & 31, wid = tid >> 5;
    const int g = lane >> 2, c = lane & 3;
    const int cg = bid >> 1;
    const int mh = bid & 1;
    const int hc0 = cg * 16;
    const int mh4 = mh * 4;

    for (int idx = tid; idx < 8192; idx += STHR) {
        int kt = idx >> 7, j2 = (idx >> 5) & 3, l = idx & 31;
        int gg = l >> 2, cc = l & 3;
        int k0 = kt * 16;
        unsigned r[4];
#pragma unroll
        for (int jj = 0; jj < 2; jj++) {
            const float* wr = g_wc + (size_t)(j2 * H_ + hc0 + jj * 8 + gg) * H_ + k0;
            r[jj * 2 + 0] = f2h2(wr[2 * cc], wr[2 * cc + 1]);
            r[jj * 2 + 1] = f2h2(wr[2 * cc + 8], wr[2 * cc + 9]);
        }
        uint4 u; u.x = r[0]; u.y = r[1]; u.z = r[2]; u.w = r[3];
        Wb[idx] = u;
    }
    for (int idx = tid; idx < 1024; idx += STHR) {
        int m = idx >> 4, hcl = idx & 15;
        c_s[m * 17 + hcl] = c0[(size_t)(mh * 64 + m) * H_ + hc0 + hcl];
    }
    __syncthreads();

    const uint4* AbW = Abuf + wid * 1024;
    const unsigned wsm = smem_u32(Abuf + wid * 1024) + lane * 16;

    for (int t = 0; t < T_; t++) {
        float acc[8][4];
#pragma unroll
        for (int j = 0; j < 8; j++)
#pragma unroll
            for (int r = 0; r < 4; r++) acc[j][r] = 0.0f;

        // prefetch xg into regs (xg fully computed before launch)
        float xgv[2][2][4][2];
        {
            const float* xgp = g_xg + (size_t)t * B_ * G_;
            int m_base = mh * 64 + wid * 16 + g;
#pragma unroll
            for (int jj = 0; jj < 2; jj++)
#pragma unroll
                for (int rr = 0; rr < 2; rr++) {
                    int m = m_base + rr * 8;
#pragma unroll
                    for (int gate = 0; gate < 4; gate++) {
                        float2 v = __ldg((const float2*)(xgp + (size_t)m * G_ +
                                          gate * H_ + hc0 + jj * 8 + 2 * c));
                        xgv[jj][rr][gate][0] = v.x;
                        xgv[jj][rr][gate][1] = v.y;
                    }
                }
        }

        if (t > 0) {
            // per-warp acquire-poll: all 128 warp-arrival counters >= 4t
            const int thr = 4 * t;
            for (;;) {
                int ok = 1;
#pragma unroll
                for (int q = 0; q < 4; q++)
                    ok &= (ld_acq(&g_flags[(lane * 4 + q) * 8]) >= thr);
                if (__all_sync(0xffffffffu, ok)) break;
            }

            const uint4* ap = g_hf + (size_t)(t - 1) * HFT + (mh4 + wid) * 32 + lane;

#pragma unroll
            for (int pc = 0; pc < 4; pc++) {
#pragma unroll
                for (int ktl = 0; ktl < 8; ktl++)
                    cp_async16(wsm + pc * 4096 + ktl * 512, ap + (pc * 8 + ktl) * 256);
                cp_commit();
            }

            for (int chk = 0; chk < 8; chk++) {
                if (chk < 5) cp_wait<3>();
                else if (chk == 5) cp_wait<2>();
                else if (chk == 6) cp_wait<1>();
                else cp_wait<0>();

                const uint4* Ab = AbW + (chk & 3) * 256;
#pragma unroll
                for (int ktl = 0; ktl < 8; ktl++) {
                    int kt = chk * 8 + ktl;
                    uint4 a = Ab[ktl * 32 + lane];
                    unsigned A[4] = {a.x, a.y, a.z, a.w};
#pragma unroll
                    for (int j2 = 0; j2 < 4; j2++) {
                        uint4 w = Wb[(kt * 4 + j2) * 32 + lane];
                        unsigned b0[2] = {w.x, w.y}, b1[2] = {w.z, w.w};
                        mma_f16(acc[2 * j2 + 0], A, b0);
                        mma_f16(acc[2 * j2 + 1], A, b1);
                    }
                }
                if (chk < 4) {
                    int pc = chk + 4;
#pragma unroll
                    for (int ktl = 0; ktl < 8; ktl++)
                        cp_async16(wsm + (pc & 3) * 4096 + ktl * 512,
                                   ap + (pc * 8 + ktl) * 256);
                    cp_commit();
                }
            }
        }

        // epilogue: fast activations + cell update + direct fp16 fragment store
        {
            unsigned frag[4];
#pragma unroll
            for (int jj = 0; jj < 2; jj++) {
#pragma unroll
                for (int rr = 0; rr < 2; rr++) {
                    int m = wid * 16 + g + rr * 8;
                    float pre[4][2];
#pragma unroll
                    for (int gate = 0; gate < 4; gate++) {
                        pre[gate][0] = acc[2 * gate + jj][rr * 2 + 0] + xgv[jj][rr][gate][0];
                        pre[gate][1] = acc[2 * gate + jj][rr * 2 + 1] + xgv[jj][rr][gate][1];
                    }
                    float hf[2];
#pragma unroll
                    for (int e = 0; e < 2; e++) {
                        float iv = fsig(pre[0][e]);
                        float fv = fsig(pre[1][e]);
                        float gv = ftanh(pre[2][e]);
                        float ov = fsig(pre[3][e]);
                        int ci = m * 17 + jj * 8 + 2 * c + e;
                        float cn = fv * c_s[ci] + iv * gv;
                        c_s[ci] = cn;
                        hf[e] = ov * ftanh(cn);
                    }
                    frag[jj * 2 + rr] = f2h2(hf[0], hf[1]);
                }
            }
            uint4 u; u.x = frag[0]; u.y = frag[1]; u.z = frag[2]; u.w = frag[3];
            g_hf[(size_t)t * HFT + ((size_t)(cg * 8 + mh4 + wid)) * 32 + lane] = u;
        }

        // publish: this warp's arrival for step t (release orders its own stores)
        if (lane == 0) red_add_rel(&g_flags[bid * 8], 1);
    }

    __syncthreads();
    const size_t ysE = (size_t)T_ * B_ * P_;
    for (int idx = tid; idx < 1024; idx += STHR) {
        int m = idx >> 4, hcl = idx & 15;
        out[ysE + B_ * P_ + (size_t)(mh * 64 + m) * H_ + hc0 + hcl] = c_s[m * 17 + hcl];
    }
}

// ---------------- Y = HFULL @ Whr^T : fp16, B frags prepacked (proven R10) ----------------
__global__ __launch_bounds__(256) void y_mma_kernel(float* __restrict__ out) {
    __shared__ uint4 Asf[1024];
    __shared__ uint2 Bsf[2048];

    const int tt = blockIdx.y;
    const int bn = blockIdx.x * 128;
    const int tid = threadIdx.x;
    const int lane = tid & 31, wid = tid >> 5;
    const int g = lane >> 2, c = lane & 3;

    float acc[16][4];
#pragma unroll
    for (int j = 0; j < 16; j++)
#pragma unroll
        for (int r = 0; r < 4; r++) acc[j][r] = 0.0f;

    const uint4* Af = g_hf + (size_t)tt * HFT;
    const uint2* Wf = g_wf + (size_t)(bn >> 7) * (64 * 16 * 32);

    for (int k0 = 0; k0 < H_; k0 += 64) {
        int ktb = k0 >> 4;
#pragma unroll
        for (int it = 0; it < 4; it++) {
            int idx = it * 256 + tid;
            Asf[idx] = Af[ktb * 256 + idx];
        }
#pragma unroll
        for (int it = 0; it < 8; it++) {
            int idx = it * 256 + tid;
            Bsf[idx] = Wf[ktb * 512 + idx];
        }
        __syncthreads();
#pragma unroll
        for (int ktl = 0; ktl < 4; ktl++) {
            uint4 av = Asf[(ktl * 8 + wid) * 32 + lane];
            unsigned A[4] = {av.x, av.y, av.z, av.w};
#pragma unroll
            for (int j = 0; j < 16; j++) {
                uint2 bv = Bsf[(ktl * 16 + j) * 32 + lane];
                unsigned B[2] = {bv.x, bv.y};
                mma_f16(acc[j], A, B);
            }
        }
        __syncthreads();
    }

    int r0 = tt * 128 + wid * 16 + g;
#pragma unroll
    for (int j = 0; j < 16; j++) {
        int n = bn + 8 * j + 2 * c;
        *(float2*)(out + (size_t)r0 * P_ + n)       = make_float2(acc[j][0], acc[j][1]);
        *(float2*)(out + (size_t)(r0 + 8) * P_ + n) = make_float2(acc[j][2], acc[j][3]);
    }
}

// ---------------- hT = ys[T-1] ----------------
__global__ void tail_kernel(float* __restrict__ out) {
    int i = blockIdx.x * blockDim.x + threadIdx.x;
    if (i < B_ * P_)
        out[(size_t)T_ * B_ * P_ + i] = out[(size_t)(T_ * B_ - B_) * P_ + i];
}

// ---------------- launch ----------------
extern "C" void kernel_launch(void* const* d_in, const int* in_sizes, int n_in,
                              void* d_out, int out_size) {
    const float* x   = (const float*)d_in[0];   // [T,B,I]
    const float* h0  = (const float*)d_in[1];   // [1,B,P]
    const float* c0  = (const float*)d_in[2];   // [1,B,H]
    const float* Wih = (const float*)d_in[3];   // [4H,I]
    const float* Whh = (const float*)d_in[4];   // [4H,P]
    const float* Whr = (const float*)d_in[5];   // [P,H]
    float* out = (float*)d_out;                 // [ys | hT | cT]

    const int seq_smem = 8192 * 16 + 4096 * 16 + 64 * 17 * 4;  // 200960 B
    static int smem_set = 0;
    if (!smem_set) {
        cudaFuncSetAttribute(lstm_seq_kernel,
                             cudaFuncAttributeMaxDynamicSharedMemorySize, seq_smem);
        smem_set = 1;
    }

    init_kernel<<<1, 1024>>>();

    dim3 gx(G_ / 128, T_);
    xg_mma_kernel<<<gx, 256>>>(x, Wih, h0, Whh);

    dim3 gw(H_ / 128, G_ / 128);
    wcomb_mma_kernel<<<gw, 256>>>(Whh, Whr);
    whr_pack_kernel<<<512, 256>>>(Whr);

    lstm_seq_kernel<<<NBLK, STHR, seq_smem>>>(c0, out);

    dim3 gy(P_ / 128, T_);
    y_mma_kernel<<<gy, 256>>>(out);
    tail_kernel<<<(B_ * P_ + 255) / 256, 256>>>(out);
}

// round 17
// speedup vs baseline: 1.1513x; 1.1513x over previous
#include <cuda_runtime.h>
#include <cuda_fp16.h>
#include <math.h>

#define T_ 256
#define B_ 128
#define I_ 1024
#define H_ 1024
#define P_ 512
#define G_ 4096  /* 4*H */

#define NBLK 128
#define STHR 128   /* recurrence kernel threads: 4 mma warps */
#define XPAD 8
#define HFT 16384  /* uint4 per timestep in g_hf: B*H fp16 /8 */

// ---------------- globals (no allocation) ----------------
__device__ float g_xg[(size_t)T_ * B_ * G_];     // [T*B, 4H] input gate contributions
__device__ float g_wc[(size_t)G_ * H_];          // W_comb = Whh @ Whr  [4096,1024] fp32
__device__ uint4 g_hf[(size_t)T_ * HFT];         // hfull, fp16 bits, k16 mma-fragment layout
__device__ uint2 g_wf[4 * 64 * 16 * 32];         // Whr fp16 B-fragments (1 MB)
__device__ int g_flags[NBLK * 8];                // per-CTA step flags (32B stride)

// ---------------- helpers ----------------
__device__ __forceinline__ unsigned f2tf(float x) {
    unsigned r;
    asm("cvt.rna.tf32.f32 %0, %1;" : "=r"(r) : "f"(x));
    return r;
}

__device__ __forceinline__ unsigned f2h2(float lo, float hi) {
    __half2 h = __floats2half2_rn(lo, hi);
    return *(unsigned*)&h;
}

__device__ __forceinline__ void mma_tf32(float* c, const unsigned* a, const unsigned* b) {
    asm volatile(
        "mma.sync.aligned.m16n8k8.row.col.f32.tf32.tf32.f32 "
        "{%0,%1,%2,%3},{%4,%5,%6,%7},{%8,%9},{%0,%1,%2,%3};"
        : "+f"(c[0]), "+f"(c[1]), "+f"(c[2]), "+f"(c[3])
        : "r"(a[0]), "r"(a[1]), "r"(a[2]), "r"(a[3]), "r"(b[0]), "r"(b[1]));
}

__device__ __forceinline__ void mma_f16(float* c, const unsigned* a, const unsigned* b) {
    asm volatile(
        "mma.sync.aligned.m16n8k16.row.col.f32.f16.f16.f32 "
        "{%0,%1,%2,%3},{%4,%5,%6,%7},{%8,%9},{%0,%1,%2,%3};"
        : "+f"(c[0]), "+f"(c[1]), "+f"(c[2]), "+f"(c[3])
        : "r"(a[0]), "r"(a[1]), "r"(a[2]), "r"(a[3]), "r"(b[0]), "r"(b[1]));
}

// fast-math epilogue transcendentals (err ~1e-5 << fp16 noise 4.2e-4)
__device__ __forceinline__ float fsig(float x) {
    float e = __expf(-x);
    return __fdividef(1.0f, 1.0f + e);
}
__device__ __forceinline__ float ftanh(float x) {
    x = fminf(fmaxf(x, -15.0f), 15.0f);
    float e = __expf(2.0f * x);
    return __fdividef(e - 1.0f, e + 1.0f);
}

__device__ __forceinline__ unsigned smem_u32(const void* p) {
    return (unsigned)__cvta_generic_to_shared(p);
}

__device__ __forceinline__ void cp_async16(unsigned dst, const void* src) {
    asm volatile("cp.async.cg.shared.global [%0], [%1], 16;" :: "r"(dst), "l"(src));
}
__device__ __forceinline__ void cp_commit() { asm volatile("cp.async.commit_group;"); }
template<int N> __device__ __forceinline__ void cp_wait() {
    asm volatile("cp.async.wait_group %0;" :: "n"(N));
}

__device__ __forceinline__ int ld_acq(const int* p) {
    int v;
    asm volatile("ld.global.acquire.gpu.b32 %0, [%1];" : "=r"(v) : "l"(p) : "memory");
    return v;
}
__device__ __forceinline__ void st_rel(int* p, int v) {
    asm volatile("st.global.release.gpu.b32 [%0], %1;" :: "l"(p), "r"(v) : "memory");
}

// ---------------- init: flag reset ----------------
__global__ void init_kernel() {
    int i = blockIdx.x * blockDim.x + threadIdx.x;
    if (i < NBLK * 8) g_flags[i] = 0;
}

// ---------------- Whr -> fp16 B-fragment pack (one-time, 1 MB) ----------------
__global__ __launch_bounds__(256) void whr_pack_kernel(const float* __restrict__ Whr) {
    int idx = blockIdx.x * 256 + threadIdx.x;
    int bn4 = idx >> 15;
    int kt  = (idx >> 9) & 63;
    int j   = (idx >> 5) & 15;
    int l   = idx & 31;
    int gg = l >> 2, cc = l & 3;
    const float* wr = Whr + (size_t)(bn4 * 128 + 8 * j + gg) * H_ + kt * 16;
    g_wf[idx] = make_uint2(f2h2(wr[2 * cc], wr[2 * cc + 1]),
                           f2h2(wr[2 * cc + 8], wr[2 * cc + 9]));
}

// ---------------- xg = x @ W_ih^T (+ h0 @ Whh^T fold for t=0) via FP16 mma ----------------
#define XAS 24
__global__ __launch_bounds__(256) void xg_mma_kernel(const float* __restrict__ X,
                                                     const float* __restrict__ Wih,
                                                     const float* __restrict__ h0,
                                                     const float* __restrict__ Whh) {
    const int K = I_, N = G_;
    __shared__ __half As[2][128][XAS];
    __shared__ __half Bs[2][128][XAS];

    const int bm = blockIdx.y * 128;
    const int bn = blockIdx.x * 128;
    const int tid = threadIdx.x;
    const int lane = tid & 31, wid = tid >> 5;
    const int wm = (wid >> 2) * 64, wn = (wid & 3) * 32;
    const int g = lane >> 2, c = lane & 3;
    const int srow = tid >> 2;
    const int skq = (tid & 3) * 4;

    float acc[4][4][4];
#pragma unroll
    for (int i = 0; i < 4; i++)
#pragma unroll
        for (int j = 0; j < 4; j++)
#pragma unroll
            for (int r = 0; r < 4; r++) acc[i][j][r] = 0.0f;

    float4 pa[2], pb[2];
#pragma unroll
    for (int it = 0; it < 2; it++) {
        int row = it * 64 + srow;
        pa[it] = *(const float4*)(X + (size_t)(bm + row) * K + skq);
        pb[it] = *(const float4*)(Wih + (size_t)(bn + row) * K + skq);
    }

    for (int kt = 0; kt < K / 16; kt++) {
        int buf = kt & 1;
#pragma unroll
        for (int it = 0; it < 2; it++) {
            int row = it * 64 + srow;
            uint2 ua, ub;
            ua.x = f2h2(pa[it].x, pa[it].y); ua.y = f2h2(pa[it].z, pa[it].w);
            ub.x = f2h2(pb[it].x, pb[it].y); ub.y = f2h2(pb[it].z, pb[it].w);
            *(uint2*)&As[buf][row][skq] = ua;
            *(uint2*)&Bs[buf][row][skq] = ub;
        }
        __syncthreads();
        if (kt < K / 16 - 1) {
            int k0 = (kt + 1) * 16;
#pragma unroll
            for (int it = 0; it < 2; it++) {
                int row = it * 64 + srow;
                pa[it] = *(const float4*)(X + (size_t)(bm + row) * K + k0 + skq);
                pb[it] = *(const float4*)(Wih + (size_t)(bn + row) * K + k0 + skq);
            }
        }
        unsigned a[4][4], b[4][2];
#pragma unroll
        for (int i = 0; i < 4; i++) {
            int m = wm + i * 16;
            a[i][0] = *(const unsigned*)&As[buf][m + g][2 * c];
            a[i][1] = *(const unsigned*)&As[buf][m + g + 8][2 * c];
            a[i][2] = *(const unsigned*)&As[buf][m + g][2 * c + 8];
            a[i][3] = *(const unsigned*)&As[buf][m + g + 8][2 * c + 8];
        }
#pragma unroll
        for (int j = 0; j < 4; j++) {
            int n = wn + j * 8;
            b[j][0] = *(const unsigned*)&Bs[buf][n + g][2 * c];
            b[j][1] = *(const unsigned*)&Bs[buf][n + g][2 * c + 8];
        }
#pragma unroll
        for (int i = 0; i < 4; i++)
#pragma unroll
            for (int j = 0; j < 4; j++) mma_f16(acc[i][j], a[i], b[j]);
    }

    // ---- t=0 fold: += h0 @ Whh^T (K=512), same staging ----
    if (bm == 0) {
        __syncthreads();
#pragma unroll
        for (int it = 0; it < 2; it++) {
            int row = it * 64 + srow;
            pa[it] = *(const float4*)(h0 + (size_t)row * P_ + skq);
            pb[it] = *(const float4*)(Whh + (size_t)(bn + row) * P_ + skq);
        }
        for (int kt = 0; kt < P_ / 16; kt++) {
            int buf = kt & 1;
#pragma unroll
            for (int it = 0; it < 2; it++) {
                int row = it * 64 + srow;
                uint2 ua, ub;
                ua.x = f2h2(pa[it].x, pa[it].y); ua.y = f2h2(pa[it].z, pa[it].w);
                ub.x = f2h2(pb[it].x, pb[it].y); ub.y = f2h2(pb[it].z, pb[it].w);
                *(uint2*)&As[buf][row][skq] = ua;
                *(uint2*)&Bs[buf][row][skq] = ub;
            }
            __syncthreads();
            if (kt < P_ / 16 - 1) {
                int k0 = (kt + 1) * 16;
#pragma unroll
                for (int it = 0; it < 2; it++) {
                    int row = it * 64 + srow;
                    pa[it] = *(const float4*)(h0 + (size_t)row * P_ + k0 + skq);
                    pb[it] = *(const float4*)(Whh + (size_t)(bn + row) * P_ + k0 + skq);
                }
            }
            unsigned a[4][4], b[4][2];
#pragma unroll
            for (int i = 0; i < 4; i++) {
                int m = wm + i * 16;
                a[i][0] = *(const unsigned*)&As[buf][m + g][2 * c];
                a[i][1] = *(const unsigned*)&As[buf][m + g + 8][2 * c];
                a[i][2] = *(const unsigned*)&As[buf][m + g][2 * c + 8];
                a[i][3] = *(const unsigned*)&As[buf][m + g + 8][2 * c + 8];
            }
#pragma unroll
            for (int j = 0; j < 4; j++) {
                int n = wn + j * 8;
                b[j][0] = *(const unsigned*)&Bs[buf][n + g][2 * c];
                b[j][1] = *(const unsigned*)&Bs[buf][n + g][2 * c + 8];
            }
#pragma unroll
            for (int i = 0; i < 4; i++)
#pragma unroll
                for (int j = 0; j < 4; j++) mma_f16(acc[i][j], a[i], b[j]);
        }
    }

#pragma unroll
    for (int i = 0; i < 4; i++) {
        int r0 = bm + wm + i * 16 + g;
#pragma unroll
        for (int j = 0; j < 4; j++) {
            int cc = bn + wn + j * 8 + c * 2;
            *(float2*)(g_xg + (size_t)r0 * N + cc)       = make_float2(acc[i][j][0], acc[i][j][1]);
            *(float2*)(g_xg + (size_t)(r0 + 8) * N + cc) = make_float2(acc[i][j][2], acc[i][j][3]);
        }
    }
}

// ---------------- W_comb = Whh @ Whr  (3xTF32, proven) ----------------
__global__ __launch_bounds__(256) void wcomb_mma_kernel(const float* __restrict__ Whh,
                                                        const float* __restrict__ Whr) {
    __shared__ unsigned Ah[16][128 + XPAD], Al[16][128 + XPAD];
    __shared__ unsigned Bh[16][128 + XPAD], Bl[16][128 + XPAD];

    const int bm = blockIdx.y * 128;
    const int bn = blockIdx.x * 128;
    const int tid = threadIdx.x;
    const int lane = tid & 31, wid = tid >> 5;
    const int wm = (wid >> 2) * 64, wn = (wid & 3) * 32;
    const int g = lane >> 2, c = lane & 3;

    float acc[4][4][4];
#pragma unroll
    for (int i = 0; i < 4; i++)
#pragma unroll
        for (int j = 0; j < 4; j++)
#pragma unroll
            for (int r = 0; r < 4; r++) acc[i][j][r] = 0.0f;

    for (int k0 = 0; k0 < P_; k0 += 16) {
#pragma unroll
        for (int it = 0; it < 2; it++) {
            int idx = it * 256 + tid;
            {
                int row = idx >> 2;
                int kq = (idx & 3) * 4;
                float4 v = *(const float4*)(Whh + (size_t)(bm + row) * P_ + k0 + kq);
                float h0 = __uint_as_float(f2tf(v.x)), h1 = __uint_as_float(f2tf(v.y));
                float h2 = __uint_as_float(f2tf(v.z)), h3 = __uint_as_float(f2tf(v.w));
                Ah[kq + 0][row] = __float_as_uint(h0); Al[kq + 0][row] = f2tf(v.x - h0);
                Ah[kq + 1][row] = __float_as_uint(h1); Al[kq + 1][row] = f2tf(v.y - h1);
                Ah[kq + 2][row] = __float_as_uint(h2); Al[kq + 2][row] = f2tf(v.z - h2);
                Ah[kq + 3][row] = __float_as_uint(h3); Al[kq + 3][row] = f2tf(v.w - h3);
            }
            {
                int k = idx >> 5;
                int n4 = (idx & 31) * 4;
                float4 v = *(const float4*)(Whr + (size_t)(k0 + k) * H_ + bn + n4);
                float h0 = __uint_as_float(f2tf(v.x)), h1 = __uint_as_float(f2tf(v.y));
                float h2 = __uint_as_float(f2tf(v.z)), h3 = __uint_as_float(f2tf(v.w));
                Bh[k][n4 + 0] = __float_as_uint(h0); Bl[k][n4 + 0] = f2tf(v.x - h0);
                Bh[k][n4 + 1] = __float_as_uint(h1); Bl[k][n4 + 1] = f2tf(v.y - h1);
                Bh[k][n4 + 2] = __float_as_uint(h2); Bl[k][n4 + 2] = f2tf(v.z - h2);
                Bh[k][n4 + 3] = __float_as_uint(h3); Bl[k][n4 + 3] = f2tf(v.w - h3);
            }
        }
        __syncthreads();
#pragma unroll
        for (int kk = 0; kk < 16; kk += 8) {
            unsigned ah[4][4], al[4][4], bh[4][2], bl[4][2];
#pragma unroll
            for (int i = 0; i < 4; i++) {
                int m = wm + i * 16;
                ah[i][0] = Ah[kk + c][m + g];     al[i][0] = Al[kk + c][m + g];
                ah[i][1] = Ah[kk + c][m + g + 8]; al[i][1] = Al[kk + c][m + g + 8];
                ah[i][2] = Ah[kk + c + 4][m + g]; al[i][2] = Al[kk + c + 4][m + g];
                ah[i][3] = Ah[kk + c + 4][m + g + 8]; al[i][3] = Al[kk + c + 4][m + g + 8];
            }
#pragma unroll
            for (int j = 0; j < 4; j++) {
                int n = wn + j * 8;
                bh[j][0] = Bh[kk + c][n + g];     bl[j][0] = Bl[kk + c][n + g];
                bh[j][1] = Bh[kk + 4 + c][n + g]; bl[j][1] = Bl[kk + 4 + c][n + g];
            }
#pragma unroll
            for (int i = 0; i < 4; i++)
#pragma unroll
                for (int j = 0; j < 4; j++) {
                    mma_tf32(acc[i][j], al[i], bh[j]);
                    mma_tf32(acc[i][j], ah[i], bl[j]);
                    mma_tf32(acc[i][j], ah[i], bh[j]);
                }
        }
        __syncthreads();
    }

#pragma unroll
    for (int i = 0; i < 4; i++) {
        int r0 = bm + wm + i * 16 + g;
#pragma unroll
        for (int j = 0; j < 4; j++) {
            int cc = bn + wn + j * 8 + c * 2;
            *(float2*)(g_wc + (size_t)r0 * H_ + cc)       = make_float2(acc[i][j][0], acc[i][j][1]);
            *(float2*)(g_wc + (size_t)(r0 + 8) * H_ + cc) = make_float2(acc[i][j][2], acc[i][j][3]);
        }
    }
}

// ---------------- persistent recurrence: R14-proven (warp-0 poll + CTA release) ----------------
__global__ __launch_bounds__(STHR, 1) void lstm_seq_kernel(const float* __restrict__ c0,
                                                           float* __restrict__ out) {
    extern __shared__ __align__(16) unsigned smraw[];
    uint4* Wb   = (uint4*)smraw;             // [8192] W frags (128 KB)
    uint4* Abuf = Wb + 8192;                 // [4 warps][4 slots][8 kt][32 lanes] (64 KB)
    float* c_s  = (float*)(Abuf + 4096);     // [64][16] stride 17 cell state

    const int bid = blockIdx.x;
    const int tid = threadIdx.x;
    const int lane = tid & 31, wid = tid >> 5;
    const int g = lane >> 2, c = lane & 3;
    const int cg = bid >> 1;
    const int mh = bid & 1;
    const int hc0 = cg * 16;
    const int mh4 = mh * 4;

    for (int idx = tid; idx < 8192; idx += STHR) {
        int kt = idx >> 7, j2 = (idx >> 5) & 3, l = idx & 31;
        int gg = l >> 2, cc = l & 3;
        int k0 = kt * 16;
        unsigned r[4];
#pragma unroll
        for (int jj = 0; jj < 2; jj++) {
            const float* wr = g_wc + (size_t)(j2 * H_ + hc0 + jj * 8 + gg) * H_ + k0;
            r[jj * 2 + 0] = f2h2(wr[2 * cc], wr[2 * cc + 1]);
            r[jj * 2 + 1] = f2h2(wr[2 * cc + 8], wr[2 * cc + 9]);
        }
        uint4 u; u.x = r[0]; u.y = r[1]; u.z = r[2]; u.w = r[3];
        Wb[idx] = u;
    }
    for (int idx = tid; idx < 1024; idx += STHR) {
        int m = idx >> 4, hcl = idx & 15;
        c_s[m * 17 + hcl] = c0[(size_t)(mh * 64 + m) * H_ + hc0 + hcl];
    }
    __syncthreads();

    const uint4* AbW = Abuf + wid * 1024;
    const unsigned wsm = smem_u32(Abuf + wid * 1024) + lane * 16;

    for (int t = 0; t < T_; t++) {
        float acc[8][4];
#pragma unroll
        for (int j = 0; j < 8; j++)
#pragma unroll
            for (int r = 0; r < 4; r++) acc[j][r] = 0.0f;

        // prefetch xg into regs
        float xgv[2][2][4][2];
        {
            const float* xgp = g_xg + (size_t)t * B_ * G_;
            int m_base = mh * 64 + wid * 16 + g;
#pragma unroll
            for (int jj = 0; jj < 2; jj++)
#pragma unroll
                for (int rr = 0; rr < 2; rr++) {
                    int m = m_base + rr * 8;
#pragma unroll
                    for (int gate = 0; gate < 4; gate++) {
                        float2 v = __ldg((const float2*)(xgp + (size_t)m * G_ +
                                          gate * H_ + hc0 + jj * 8 + 2 * c));
                        xgv[jj][rr][gate][0] = v.x;
                        xgv[jj][rr][gate][1] = v.y;
                    }
                }
        }

        if (t > 0) {
            // warp-0 acquire-poll of all 128 flags (4 per lane), then CTA-wide release
            if (wid == 0) {
                for (;;) {
                    int ok = 1;
#pragma unroll
                    for (int q = 0; q < 4; q++)
                        ok &= (ld_acq(&g_flags[(lane * 4 + q) * 8]) >= t);
                    if (__all_sync(0xffffffffu, ok)) break;
                }
            }
            __syncthreads();

            const uint4* ap = g_hf + (size_t)(t - 1) * HFT + (mh4 + wid) * 32 + lane;

#pragma unroll
            for (int pc = 0; pc < 4; pc++) {
#pragma unroll
                for (int ktl = 0; ktl < 8; ktl++)
                    cp_async16(wsm + pc * 4096 + ktl * 512, ap + (pc * 8 + ktl) * 256);
                cp_commit();
            }

            for (int chk = 0; chk < 8; chk++) {
                if (chk < 5) cp_wait<3>();
                else if (chk == 5) cp_wait<2>();
                else if (chk == 6) cp_wait<1>();
                else cp_wait<0>();

                const uint4* Ab = AbW + (chk & 3) * 256;
#pragma unroll
                for (int ktl = 0; ktl < 8; ktl++) {
                    int kt = chk * 8 + ktl;
                    uint4 a = Ab[ktl * 32 + lane];
                    unsigned A[4] = {a.x, a.y, a.z, a.w};
#pragma unroll
                    for (int j2 = 0; j2 < 4; j2++) {
                        uint4 w = Wb[(kt * 4 + j2) * 32 + lane];
                        unsigned b0[2] = {w.x, w.y}, b1[2] = {w.z, w.w};
                        mma_f16(acc[2 * j2 + 0], A, b0);
                        mma_f16(acc[2 * j2 + 1], A, b1);
                    }
                }
                if (chk < 4) {
                    int pc = chk + 4;
#pragma unroll
                    for (int ktl = 0; ktl < 8; ktl++)
                        cp_async16(wsm + (pc & 3) * 4096 + ktl * 512,
                                   ap + (pc * 8 + ktl) * 256);
                    cp_commit();
                }
            }
        }

        // epilogue: fast activations + cell update + direct fp16 fragment store
        {
            unsigned frag[4];
#pragma unroll
            for (int jj = 0; jj < 2; jj++) {
#pragma unroll
                for (int rr = 0; rr < 2; rr++) {
                    int m = wid * 16 + g + rr * 8;
                    float pre[4][2];
#pragma unroll
                    for (int gate = 0; gate < 4; gate++) {
                        pre[gate][0] = acc[2 * gate + jj][rr * 2 + 0] + xgv[jj][rr][gate][0];
                        pre[gate][1] = acc[2 * gate + jj][rr * 2 + 1] + xgv[jj][rr][gate][1];
                    }
                    float hf[2];
#pragma unroll
                    for (int e = 0; e < 2; e++) {
                        float iv = fsig(pre[0][e]);
                        float fv = fsig(pre[1][e]);
                        float gv = ftanh(pre[2][e]);
                        float ov = fsig(pre[3][e]);
                        int ci = m * 17 + jj * 8 + 2 * c + e;
                        float cn = fv * c_s[ci] + iv * gv;
                        c_s[ci] = cn;
                        hf[e] = ov * ftanh(cn);
                    }
                    frag[jj * 2 + rr] = f2h2(hf[0], hf[1]);
                }
            }
            uint4 u; u.x = frag[0]; u.y = frag[1]; u.z = frag[2]; u.w = frag[3];
            g_hf[(size_t)t * HFT + ((size_t)(cg * 8 + mh4 + wid)) * 32 + lane] = u;
        }

        // publish step t: release store after CTA-wide join
        __syncthreads();
        if (tid == 0) st_rel(&g_flags[bid * 8], t + 1);
    }

    const size_t ysE = (size_t)T_ * B_ * P_;
    for (int idx = tid; idx < 1024; idx += STHR) {
        int m = idx >> 4, hcl = idx & 15;
        out[ysE + B_ * P_ + (size_t)(mh * 64 + m) * H_ + hc0 + hcl] = c_s[m * 17 + hcl];
    }
}

// ---------------- Y = HFULL @ Whr^T : fp16, double-buffered cp.async pipeline ----------------
// Per iter (k64): A chunk = g_hf[tt*HFT + i*1024 ..+1024] (16 KB), B chunk = g_wf4[i*1024 ..+1024]
// (16 KB), both contiguous. Issue i+1 overlaps compute i; ONE syncthreads per iter.
__global__ __launch_bounds__(256) void y_mma_kernel(float* __restrict__ out) {
    extern __shared__ __align__(16) uint4 ysm[];   // [2][1024] A + [2][1024] B = 64 KB
    uint4* Abuf = ysm;
    uint4* Bbuf = ysm + 2048;

    const int tt = blockIdx.y;
    const int bn = blockIdx.x * 128;
    const int tid = threadIdx.x;
    const int lane = tid & 31, wid = tid >> 5;
    const int g = lane >> 2, c = lane & 3;

    float acc[16][4];
#pragma unroll
    for (int j = 0; j < 16; j++)
#pragma unroll
        for (int r = 0; r < 4; r++) acc[j][r] = 0.0f;

    const uint4* Af  = g_hf + (size_t)tt * HFT;
    const uint4* Wf4 = (const uint4*)(g_wf + (size_t)(bn >> 7) * (64 * 16 * 32));

    const unsigned sA = smem_u32(Abuf);
    const unsigned sB = smem_u32(Bbuf);

    // prologue: issue iter 0
#pragma unroll
    for (int it = 0; it < 4; it++) {
        int idx = it * 256 + tid;
        cp_async16(sA + idx * 16, Af + idx);
        cp_async16(sB + idx * 16, Wf4 + idx);
    }
    cp_commit();

    for (int i = 0; i < 16; i++) {
        cp_wait<0>();
        __syncthreads();
        if (i < 15) {
            int b = (i + 1) & 1;
#pragma unroll
            for (int it = 0; it < 4; it++) {
                int idx = it * 256 + tid;
                cp_async16(sA + (b * 1024 + idx) * 16, Af + (i + 1) * 1024 + idx);
                cp_async16(sB + (b * 1024 + idx) * 16, Wf4 + (i + 1) * 1024 + idx);
            }
            cp_commit();
        }
        const uint4* Ai = Abuf + (i & 1) * 1024;
        const uint2* Bi = (const uint2*)(Bbuf + (i & 1) * 1024);
#pragma unroll
        for (int ktl = 0; ktl < 4; ktl++) {
            uint4 av = Ai[(ktl * 8 + wid) * 32 + lane];
            unsigned A[4] = {av.x, av.y, av.z, av.w};
#pragma unroll
            for (int j = 0; j < 16; j++) {
                uint2 bv = Bi[(ktl * 16 + j) * 32 + lane];
                unsigned B[2] = {bv.x, bv.y};
                mma_f16(acc[j], A, B);
            }
        }
    }

    int r0 = tt * 128 + wid * 16 + g;
#pragma unroll
    for (int j = 0; j < 16; j++) {
        int n = bn + 8 * j + 2 * c;
        *(float2*)(out + (size_t)r0 * P_ + n)       = make_float2(acc[j][0], acc[j][1]);
        *(float2*)(out + (size_t)(r0 + 8) * P_ + n) = make_float2(acc[j][2], acc[j][3]);
    }
}

// ---------------- hT = ys[T-1] ----------------
__global__ void tail_kernel(float* __restrict__ out) {
    int i = blockIdx.x * blockDim.x + threadIdx.x;
    if (i < B_ * P_)
        out[(size_t)T_ * B_ * P_ + i] = out[(size_t)(T_ * B_ - B_) * P_ + i];
}

// ---------------- launch ----------------
extern "C" void kernel_launch(void* const* d_in, const int* in_sizes, int n_in,
                              void* d_out, int out_size) {
    const float* x   = (const float*)d_in[0];   // [T,B,I]
    const float* h0  = (const float*)d_in[1];   // [1,B,P]
    const float* c0  = (const float*)d_in[2];   // [1,B,H]
    const float* Wih = (const float*)d_in[3];   // [4H,I]
    const float* Whh = (const float*)d_in[4];   // [4H,P]
    const float* Whr = (const float*)d_in[5];   // [P,H]
    float* out = (float*)d_out;                 // [ys | hT | cT]

    const int seq_smem = 8192 * 16 + 4096 * 16 + 64 * 17 * 4;  // 200960 B
    const int y_smem = 4096 * 16;                              // 65536 B
    static int smem_set = 0;
    if (!smem_set) {
        cudaFuncSetAttribute(lstm_seq_kernel,
                             cudaFuncAttributeMaxDynamicSharedMemorySize, seq_smem);
        cudaFuncSetAttribute(y_mma_kernel,
                             cudaFuncAttributeMaxDynamicSharedMemorySize, y_smem);
        smem_set = 1;
    }

    init_kernel<<<1, 1024>>>();

    dim3 gx(G_ / 128, T_);
    xg_mma_kernel<<<gx, 256>>>(x, Wih, h0, Whh);

    dim3 gw(H_ / 128, G_ / 128);
    wcomb_mma_kernel<<<gw, 256>>>(Whh, Whr);
    whr_pack_kernel<<<512, 256>>>(Whr);

    lstm_seq_kernel<<<NBLK, STHR, seq_smem>>>(c0, out);

    dim3 gy(P_ / 128, T_);
    y_mma_kernel<<<gy, 256, y_smem>>>(out);
    tail_kernel<<<(B_ * P_ + 255) / 256, 256>>>(out);
}